// round 4
// baseline (speedup 1.0000x reference)
#include <cuda_runtime.h>
#include <math.h>

#define NN 2048
#define DD 128
#define KK 16
#define EE 8192
#define ROWS 2064               // 2048 phi rows + 16 beta rows
#define CNT 262144.0

__device__ float g_s[2][ROWS*DD];     // phi_s rows 0..2047, beta_s rows 2048..2063
__device__ float g_h[2][ROWS*DD];
__device__ float g_G[ROWS*512];
__device__ float g_Hm[ROWS*256];
__device__ float g_M[NN*KK];          // n-major, k contiguous
__device__ float g_W1n[512*256], g_W1c[512*256];
__device__ float g_b1n[512],     g_b1c[512];
__device__ float g_W2n[256*DD],  g_W2c[256*DD];
__device__ float g_b2n[256],     g_b2c[256];
__device__ float g_am[DD];
__device__ double g_acc[5];           // nll, kldz, kldb, kldp, kld_alpha

__device__ __forceinline__ float fsig(float x){ return 1.f/(1.f+__expf(-x)); }
__device__ __forceinline__ float ftanh(float x){
    float e=__expf(fminf(fmaxf(2.f*x,-30.f),30.f)); return (e-1.f)/(e+1.f); }
__device__ __forceinline__ float fsoftplus(float x){
    return fmaxf(x,0.f)+log1pf(__expf(-fabsf(x))); }

__global__ void k_init0(const int* sidx,const float* am,const float* as){
    int t=threadIdx.x; int s=sidx[0];
    __shared__ float red[128];
    float m=am[(size_t)s*DD+t];
    float sd=fsoftplus(as[(size_t)s*DD+t]);
    g_am[t]=m;
    red[t]=0.5f*(-2.f*logf(sd)+sd*sd+m*m-1.f);
    __syncthreads();
    for(int o=64;o;o>>=1){ if(t<o) red[t]+=red[t+o]; __syncthreads(); }
    if(t==0){ g_acc[4]=(double)red[0]; g_acc[0]=g_acc[1]=g_acc[2]=g_acc[3]=0.0; }
}

__global__ void k_initW(const float* WihN,const float* WhhN,const float* bihN,const float* bhhN,
                        const float* WihC,const float* WhhC,const float* bihC,const float* bhhC,
                        const float* Wpm,const float* bpm,const float* Wps,const float* bps,
                        const float* Wbm,const float* bbm,const float* Wbs,const float* bbs){
    int i=blockIdx.x*256+threadIdx.x;
    if(i<131072){                                  // W1 (both paths), 512 x 256
        int j=i>>8, c=i&255; float vn,vc;
        if(j<256){
            vn = c<128 ? WihN[j*256+c]+WihN[j*256+128+c] : WhhN[j*128+c-128];
            vc = c<128 ? WihC[j*256+c]+WihC[j*256+128+c] : WhhC[j*128+c-128];
        } else if(j<384){
            vn = c<128 ? WihN[j*256+c]+WihN[j*256+128+c] : 0.f;
            vc = c<128 ? WihC[j*256+c]+WihC[j*256+128+c] : 0.f;
        } else { int jr=j-128;
            vn = c<128 ? 0.f : WhhN[jr*128+c-128];
            vc = c<128 ? 0.f : WhhC[jr*128+c-128];
        }
        g_W1n[i]=vn; g_W1c[i]=vc;
    } else if(i<163840){                           // W2, 256 x 128
        int o=i-131072, r=o>>7, c=o&127;
        g_W2n[o] = r<128 ? Wpm[r*128+c] : Wps[(r-128)*128+c];
        g_W2c[o] = r<128 ? Wbm[r*128+c] : Wbs[(r-128)*128+c];
    } else if(i<164352){                           // b1
        int j=i-163840; float bn,bc;
        if(j<256){ bn=bihN[j]+bhhN[j]; bc=bihC[j]+bhhC[j]; }
        else if(j<384){ bn=bihN[j]; bc=bihC[j]; }
        else { bn=bhhN[j-128]; bc=bhhC[j-128]; }
        g_b1n[j]=bn; g_b1c[j]=bc;
    } else if(i<164608){                           // b2
        int j=i-164352;
        g_b2n[j] = j<128 ? bpm[j] : bps[j-128];
        g_b2c[j] = j<128 ? bbm[j] : bbs[j-128];
    }
}

__global__ void k_initS(const float* Wp,const float* bp,const float* Wb,const float* bb){
    __shared__ float am[DD];
    int tid=threadIdx.x;
    if(tid<DD) am[tid]=g_am[tid];
    __syncthreads();
    int i=blockIdx.x*256+tid; if(i>=ROWS*DD) return;
    const float* wr; float bias;
    if(i<NN*DD){ wr=Wp+(size_t)i*DD; bias=bp[i]; }
    else { int o=i-NN*DD; wr=Wb+(size_t)o*DD; bias=bb[o]; }
    const float4* w4=(const float4*)wr; const float4* a4=(const float4*)am;
    float acc=bias;
    #pragma unroll 8
    for(int q=0;q<32;q++){ float4 w=w4[q],a=a4[q];
        acc+=w.x*a.x+w.y*a.y+w.z*a.z+w.w*a.w; }
    g_s[0][i]=acc; g_h[0][i]=0.f;
}

// C = A @ W^T + b, tiled 32x64, KD inner.  KD=256: gates.  KD=128: heads.
template<int KD>
__global__ void k_gemm(int pp){
    extern __shared__ float sm[];
    float* As=sm; float* Ws=sm+32*(KD+1);
    int mT=blockIdx.x, pT=blockIdx.y, tid=threadIdx.x;
    int beta=(mT==64);
    int row0=beta?2048:mT*32, rowsEff=beta?16:32, p0=pT*64;
    const float *A0,*A1,*W,*bias; float* C; int ldC;
    if(KD==256){ A0=g_s[pp]; A1=g_h[pp]; W=beta?g_W1c:g_W1n; bias=beta?g_b1c:g_b1n; C=g_G; ldC=512; }
    else       { A0=g_h[1-pp]; A1=0;     W=beta?g_W2c:g_W2n; bias=beta?g_b2c:g_b2n; C=g_Hm; ldC=256; }
    for(int i=tid;i<32*KD;i+=256){ int r=i/KD,c=i-r*KD; float v=0.f;
        if(r<rowsEff){ int g=(row0+r)*DD+(c&127); v=(KD==256&&c>=128)?A1[g]:A0[g]; }
        As[r*(KD+1)+c]=v; }
    for(int i=tid;i<64*KD;i+=256){ int r=i/KD,c=i-r*KD;
        Ws[r*(KD+1)+c]=W[(size_t)(p0+r)*KD+c]; }
    __syncthreads();
    int rm=(tid&7)*4, cp=(tid>>3)*2;
    float a00=0,a01=0,a10=0,a11=0,a20=0,a21=0,a30=0,a31=0;
    #pragma unroll 4
    for(int d=0;d<KD;d++){
        float w0=Ws[cp*(KD+1)+d], w1=Ws[(cp+1)*(KD+1)+d];
        float x0=As[(rm+0)*(KD+1)+d], x1=As[(rm+1)*(KD+1)+d];
        float x2=As[(rm+2)*(KD+1)+d], x3=As[(rm+3)*(KD+1)+d];
        a00+=x0*w0; a01+=x0*w1; a10+=x1*w0; a11+=x1*w1;
        a20+=x2*w0; a21+=x2*w1; a30+=x3*w0; a31+=x3*w1;
    }
    float b0=bias[p0+cp], b1=bias[p0+cp+1];
    float r0[4]={a00,a10,a20,a30}, r1[4]={a01,a11,a21,a31};
    for(int i=0;i<4;i++){ int r=rm+i; if(r<rowsEff){
        C[(size_t)(row0+r)*ldC+p0+cp]=r0[i]+b0;
        C[(size_t)(row0+r)*ldC+p0+cp+1]=r1[i]+b1; } }
}

__global__ void k_act(int pp){
    int i=blockIdx.x*256+threadIdx.x; if(i>=ROWS*DD) return;
    int row=i>>7, d=i&127;
    const float* G=g_G+(size_t)row*512;
    float r=fsig(G[d]), z=fsig(G[128+d]);
    float nn=ftanh(G[256+d]+r*G[384+d]);
    g_h[1-pp][i]=(1.f-z)*nn+z*g_h[pp][i];
}

__global__ void k_sample(int pp,const float* ept,const float* ebt){
    int i=blockIdx.x*256+threadIdx.x;
    double kp=0,kb=0;
    if(i<ROWS*DD){
        int row=i>>7, d=i&127;
        float mean=g_Hm[row*256+d];
        float sd=fsoftplus(g_Hm[row*256+128+d]);
        float prior=g_s[pp][i];
        float e = row<NN ? ept[i] : ebt[(row-NN)*DD+d];
        g_s[1-pp][i]=mean+sd*e;
        float dm=mean-prior;
        if(row<NN) kp=0.5*(-2.0*(double)logf(sd)+(double)sd*sd+(double)dm*dm-1.0);
        else       kb=0.5*(2.0*(-2.302585092994046-(double)logf(sd))
                          +((double)sd*sd+(double)dm*dm)*100.0-1.0);
    }
    __shared__ double r1[256],r2[256];
    int t=threadIdx.x; r1[t]=kp; r2[t]=kb; __syncthreads();
    for(int o=128;o;o>>=1){ if(t<o){ r1[t]+=r1[t+o]; r2[t]+=r2[t+o]; } __syncthreads(); }
    if(t==0){ if(r1[0]!=0.0) atomicAdd(&g_acc[3],r1[0]);
              if(r2[0]!=0.0) atomicAdd(&g_acc[2],r2[0]); }
}

__global__ void k_matM(int pp,const float* Wdec){
    __shared__ float bs[KK*DD];
    int t=threadIdx.x, po=1-pp;
    for(int i=t;i<KK*DD;i+=256) bs[i]=g_s[po][NN*DD+i];
    __syncthreads();
    int n=blockIdx.x*256+t;
    float acc[KK]; for(int k=0;k<KK;k++) acc[k]=0.f;
    const float4* w4=(const float4*)(Wdec+(size_t)n*DD);
    for(int q=0;q<32;q++){ float4 w=w4[q];
        #pragma unroll
        for(int k=0;k<KK;k++){ float4 b=((const float4*)(bs+k*DD))[q];
            acc[k]+=w.x*b.x+w.y*b.y+w.z*b.z+w.w*b.w; } }
    #pragma unroll
    for(int k=0;k<KK;k++) g_M[n*KK+k]=acc[k];
}

__global__ void k_edgelse(int pp,const int* edt,const float* ut,const float* Wpi){
    extern __shared__ float sm[];
    float* Ms=sm; float* Pt=sm+NN*KK; float* Bt=Pt+DD*KK;
    int t=threadIdx.x, po=1-pp;
    for(int i=t;i<NN*KK;i+=128) Ms[i]=g_M[i];
    for(int i=t;i<DD*KK;i+=128){ int d=i>>4,k=i&15;
        Pt[i]=Wpi[k*DD+d]; Bt[i]=g_s[po][NN*DD+k*DD+d]; }
    __syncthreads();
    int e=blockIdx.x*128+t, w,c;
    if(e<EE){ w=edt[2*e]; c=edt[2*e+1]; } else { int e2=e-EE; w=edt[2*e2+1]; c=edt[2*e2]; }
    const float4* pw4=(const float4*)(g_s[po]+(size_t)w*DD);
    const float4* pc4=(const float4*)(g_s[po]+(size_t)c*DD);
    float lq[KK],lp[KK];
    #pragma unroll
    for(int k=0;k<KK;k++){ lq[k]=0.f; lp[k]=0.f; }
    for(int q=0;q<32;q++){
        float4 a=pw4[q], b=pc4[q];
        float pr[4]={a.x*b.x,a.y*b.y,a.z*b.z,a.w*b.w};
        float aw[4]={a.x,a.y,a.z,a.w};
        #pragma unroll
        for(int j=0;j<4;j++){ int d=q*4+j;
            #pragma unroll
            for(int k=0;k<KK;k++){ lq[k]+=pr[j]*Pt[d*KK+k]; lp[k]+=aw[j]*Bt[d*KK+k]; } }
    }
    float mq=-3e38f,mp=-3e38f;
    #pragma unroll
    for(int k=0;k<KK;k++){ mq=fmaxf(mq,lq[k]); mp=fmaxf(mp,lp[k]); }
    float sq=0,sp=0;
    #pragma unroll
    for(int k=0;k<KK;k++){ sq+=__expf(lq[k]-mq); sp+=__expf(lp[k]-mp); }
    float lsq=__logf(sq), lsp=__logf(sp), kz=0.f;
    #pragma unroll
    for(int k=0;k<KK;k++){ float lpo=lq[k]-mq-lsq;
        kz+=__expf(lpo)*(lpo-(lp[k]-mp-lsp)); }
    const float4* u4=(const float4*)(ut+(size_t)e*KK);
    float ze[KK];
    #pragma unroll
    for(int q=0;q<4;q++){ float4 u=u4[q]; float uu[4]={u.x,u.y,u.z,u.w};
        #pragma unroll
        for(int j=0;j<4;j++)
            ze[q*4+j]=lq[q*4+j]-__logf(-__logf(uu[j]+1e-10f)+1e-10f); }
    float mz=-3e38f;
    #pragma unroll
    for(int k=0;k<KK;k++) mz=fmaxf(mz,ze[k]);
    float sz=0;
    #pragma unroll
    for(int k=0;k<KK;k++){ ze[k]=__expf(ze[k]-mz); sz+=ze[k]; }
    float inv=1.f/sz;
    #pragma unroll
    for(int k=0;k<KK;k++) ze[k]*=inv;
    float m=-3e38f,s=0.f,vc=0.f;
    for(int n=0;n<NN;n++){
        const float4* mr=(const float4*)(Ms+n*KK);
        float4 r0=mr[0],r1=mr[1],r2=mr[2],r3=mr[3];
        float v = ze[0]*r0.x+ze[1]*r0.y+ze[2]*r0.z+ze[3]*r0.w
                + ze[4]*r1.x+ze[5]*r1.y+ze[6]*r1.z+ze[7]*r1.w
                + ze[8]*r2.x+ze[9]*r2.y+ze[10]*r2.z+ze[11]*r2.w
                + ze[12]*r3.x+ze[13]*r3.y+ze[14]*r3.z+ze[15]*r3.w;
        float mn=fmaxf(m,v);
        s=s*__expf(m-mn)+__expf(v-mn);
        m=mn;
        vc = (n==c)? v : vc;
    }
    float nll=-(vc-m-__logf(s));
    __shared__ double rd[128];
    rd[t]=(double)nll; __syncthreads();
    for(int o=64;o;o>>=1){ if(t<o) rd[t]+=rd[t+o]; __syncthreads(); }
    if(t==0) atomicAdd(&g_acc[0],rd[0]);
    __syncthreads();
    rd[t]=(double)kz; __syncthreads();
    for(int o=64;o;o>>=1){ if(t<o) rd[t]+=rd[t+o]; __syncthreads(); }
    if(t==0) atomicAdd(&g_acc[1],rd[0]);
}

__global__ void k_out(float* out){
    out[0]=(float)(g_acc[0]/CNT);
    out[1]=(float)(g_acc[1]/CNT);
    out[2]=(float)(16.0*g_acc[4]/CNT);
    out[3]=(float)(g_acc[2]/CNT);
    out[4]=(float)(g_acc[3]/CNT);
}

extern "C" void kernel_launch(void* const* d_in,const int* in_sizes,int n_in,
                              void* d_out,int out_size){
    const int*   edges=(const int*)d_in[0];
    const int*   sidx =(const int*)d_in[1];
    const float* epp  =(const float*)d_in[2];
    const float* epb  =(const float*)d_in[3];
    const float* ug   =(const float*)d_in[4];
    const float* amean=(const float*)d_in[5];
    const float* astd =(const float*)d_in[6];
    const float* Ws2p =(const float*)d_in[7];  const float* bs2p=(const float*)d_in[8];
    const float* Ws2b =(const float*)d_in[9];  const float* bs2b=(const float*)d_in[10];
    const float* Wbm  =(const float*)d_in[11]; const float* bbm =(const float*)d_in[12];
    const float* Wbs  =(const float*)d_in[13]; const float* bbs =(const float*)d_in[14];
    const float* Wpm  =(const float*)d_in[15]; const float* bpm =(const float*)d_in[16];
    const float* Wps  =(const float*)d_in[17]; const float* bps =(const float*)d_in[18];
    const float* Wpi  =(const float*)d_in[19];
    const float* WihN =(const float*)d_in[20]; const float* WhhN=(const float*)d_in[21];
    const float* bihN =(const float*)d_in[22]; const float* bhhN=(const float*)d_in[23];
    const float* WihC =(const float*)d_in[24]; const float* WhhC=(const float*)d_in[25];
    const float* bihC =(const float*)d_in[26]; const float* bhhC=(const float*)d_in[27];
    const float* Wdec =(const float*)d_in[28];
    float* out=(float*)d_out;

    cudaFuncSetAttribute(k_gemm<256>,cudaFuncAttributeMaxDynamicSharedMemorySize,98688);
    cudaFuncSetAttribute(k_gemm<128>,cudaFuncAttributeMaxDynamicSharedMemorySize,49536);
    cudaFuncSetAttribute(k_edgelse,  cudaFuncAttributeMaxDynamicSharedMemorySize,147456);

    k_init0<<<1,128>>>(sidx,amean,astd);
    k_initW<<<644,256>>>(WihN,WhhN,bihN,bhhN,WihC,WhhC,bihC,bhhC,
                         Wpm,bpm,Wps,bps,Wbm,bbm,Wbs,bbs);
    k_initS<<<1033,256>>>(Ws2p,bs2p,Ws2b,bs2b);
    for(int t=0;t<16;t++){
        int pp=t&1;
        k_gemm<256><<<dim3(65,8),256,98688>>>(pp);
        k_act<<<1033,256>>>(pp);
        k_gemm<128><<<dim3(65,4),256,49536>>>(pp);
        k_sample<<<1033,256>>>(pp, epp+(size_t)t*NN*DD, epb+(size_t)t*KK*DD);
        k_matM<<<8,256>>>(pp, Wdec);
        k_edgelse<<<128,128,147456>>>(pp, edges+(size_t)t*EE*2,
                                      ug+(size_t)t*2*EE*KK, Wpi);
    }
    k_out<<<1,1>>>(out);
}